// round 13
// baseline (speedup 1.0000x reference)
#include <cuda_runtime.h>

#define NL 4
#define BATCH 16384
#define THREADS 512
#define EPB 32
#define NBLK (BATCH / EPB)
#define XS_S 68          // xs row stride (floats)
#define XC_S 132         // xc/sz row stride (floats / u32)
#define XH_S 36          // split-xs row stride (u32)
#define PROJ_S 72        // proj scratch row stride (floats)
#define NCHUNK 16        // fold c-split
#define EPSV 1e-5f

typedef unsigned long long ull;
typedef unsigned int u32;

__device__ __forceinline__ ull pk2(float lo, float hi) {
    ull r; asm("mov.b64 %0,{%1,%2};" : "=l"(r) : "f"(lo), "f"(hi)); return r;
}
__device__ __forceinline__ void upk2(ull v, float& lo, float& hi) {
    asm("mov.b64 {%0,%1},%2;" : "=f"(lo), "=f"(hi) : "l"(v));
}
__device__ __forceinline__ ull ffma2(ull a, ull b, ull c) {
    ull d; asm("fma.rn.f32x2 %0,%1,%2,%3;" : "=l"(d) : "l"(a), "l"(b), "l"(c)); return d;
}
__device__ __forceinline__ float warp_sum(float v) {
    v += __shfl_xor_sync(0xffffffffu, v, 16);
    v += __shfl_xor_sync(0xffffffffu, v, 8);
    v += __shfl_xor_sync(0xffffffffu, v, 4);
    v += __shfl_xor_sync(0xffffffffu, v, 2);
    v += __shfl_xor_sync(0xffffffffu, v, 1);
    return v;
}
__device__ __forceinline__ float half_sum(float v) {
    v += __shfl_xor_sync(0xffffffffu, v, 8);
    v += __shfl_xor_sync(0xffffffffu, v, 4);
    v += __shfl_xor_sync(0xffffffffu, v, 2);
    v += __shfl_xor_sync(0xffffffffu, v, 1);
    return v;
}
__device__ __forceinline__ void group_bar(int q) {
    asm volatile("bar.sync %0, 128;" :: "r"(q + 1) : "memory");
}
__device__ __forceinline__ float siluf(float v) {
    return __fdividef(v, 1.0f + __expf(-v));
}
__device__ __forceinline__ float softplusf(float v) {
    return fmaxf(v, 0.0f) + __logf(1.0f + __expf(-fabsf(v)));
}
__device__ __forceinline__ float fget(float4 v, int r) {
    return r == 0 ? v.x : r == 1 ? v.y : r == 2 ? v.z : v.w;
}
__device__ __forceinline__ u32 uget(uint4 v, int r) {
    return r == 0 ? v.x : r == 1 ? v.y : r == 2 ? v.z : v.w;
}
// split two fp32 (p.x = even k, p.y = odd k) into packed bf16x2 hi + lo
__device__ __forceinline__ void bfsplit(float2 p, u32& h, u32& l) {
    asm("cvt.rn.satfinite.bf16x2.f32 %0,%1,%2;" : "=r"(h) : "f"(p.y), "f"(p.x));
    float h0 = __uint_as_float(h << 16);
    float h1 = __uint_as_float(h & 0xffff0000u);
    asm("cvt.rn.satfinite.bf16x2.f32 %0,%1,%2;" : "=r"(l) : "f"(p.y - h1), "f"(p.x - h0));
}
__device__ __forceinline__ void mma_bf16(float* c, const u32* a, u32 b0, u32 b1) {
    asm("mma.sync.aligned.m16n8k16.row.col.f32.bf16.bf16.f32 "
        "{%0,%1,%2,%3},{%4,%5,%6,%7},{%8,%9},{%0,%1,%2,%3};"
        : "+f"(c[0]), "+f"(c[1]), "+f"(c[2]), "+f"(c[3])
        : "r"(a[0]), "r"(a[1]), "r"(a[2]), "r"(a[3]), "r"(b0), "r"(b1));
}
// permuted position of word w (0..31) within an xs-split row
__device__ __forceinline__ int posA(int w) {
    return (w & 3) * 8 + (w >> 3) * 2 + ((w >> 2) & 1);
}
// permuted position of word w (0..63) within an xc-half
__device__ __forceinline__ int pos64(int w) {
    int c = w & 3, e = (w >> 2) & 1, k = w >> 3;
    int j = k * 2 + e;
    int slot = ((j >> 2) + 2 * (c >> 1)) & 3;
    return c * 16 + slot * 4 + (j & 3);
}
#define CP_ASYNC16(dst_u32, src_ptr) \
    asm volatile("cp.async.cg.shared.global [%0], [%1], 16;" \
                 :: "r"(dst_u32), "l"(src_ptr) : "memory")
#define CP_COMMIT() asm volatile("cp.async.commit_group;" ::: "memory")
#define CP_WAIT0()  asm volatile("cp.async.wait_group 0;" ::: "memory")

// ---------- per-layer weight blob: FRAGMENT-ORDER packing (unchanged R12) ----------
struct __align__(16) LayerBlob {
    u32 ipwPh[4 * 4 * 32 * 16];
    u32 ipwPl[4 * 4 * 32 * 16];
    u32 opwPh[8 * 4 * 32 * 4];
    u32 opwPl[8 * 4 * 32 * 4];
    u32 xpjPh[8 * 5 * 32 * 2];
    u32 xpjPl[8 * 5 * 32 * 2];
    float dtw[4 * 128];
    float cw3[128];
    float cb[128];
    float dtb[128];
    float dskip[128];
    float lng[64];
    float lnb[64];
};   // 123,392 B

#define BLOB_V4 (sizeof(LayerBlob) / 16)

__device__ LayerBlob g_blob[NL];
__device__ float g_fold_part[18 * NCHUNK * 64];

#define FOLD_BLKS (18 * NCHUNK)
#define B0 (NL * 8192)
#define B1 (B0 + NL * 4096)
#define B2 (B1 + NL * 2560)
#define B3 (B2 + NL * 512)
#define B4 (B3 + NL * 128)
#define B5 (B4 + NL * 128)
#define B6 (B5 + NL * 128)
#define B7 (B6 + NL * 128)
#define B8 (B7 + NL * 64)
#define B9 (B8 + NL * 64)
#define BLOB_BLKS ((B9 + 255) / 256)

__global__ void __launch_bounds__(256)
prep_all(const float* __restrict__ w_nr, const float* __restrict__ b_nr,
         const float* __restrict__ w_r,  const float* __restrict__ b_r,
         const float* __restrict__ w_in_nr, const float* __restrict__ w_in_r,
         const float* __restrict__ ipw, const float* __restrict__ opw,
         const float* __restrict__ xpw, const float* __restrict__ dtw,
         const float* __restrict__ cw,  const float* __restrict__ cb,
         const float* __restrict__ dtb, const float* __restrict__ dskip,
         const float* __restrict__ lng, const float* __restrict__ lnb) {
    if (blockIdx.x < FOLD_BLKS) {
        __shared__ float red[4][64];
        const int j = blockIdx.x / NCHUNK;
        const int chunk = blockIdx.x - j * NCHUNK;
        const int o = threadIdx.x & 63;
        const int cg = threadIdx.x >> 6;
        const float* vec;
        const float* mat;
        if (j < 12)       { vec = w_nr + j * 1000;        mat = w_in_nr; }
        else if (j == 12) { vec = b_nr;                   mat = w_in_nr; }
        else if (j < 17)  { vec = w_r + (j - 13) * 1000;  mat = w_in_r;  }
        else              { vec = b_r;                    mat = w_in_r;  }
        const int cbase = chunk * 63;
        const int cend = (cbase + 63 < 1000) ? cbase + 63 : 1000;
        float a0 = 0.f, a1 = 0.f;
        for (int c = cbase + cg * 2; c < cend; c += 8) {
            a0 = fmaf(vec[c], mat[c * 64 + o], a0);
            if (c + 1 < cend)
                a1 = fmaf(vec[c + 1], mat[(c + 1) * 64 + o], a1);
        }
        red[cg][o] = a0 + a1;
        __syncthreads();
        if (cg == 0)
            g_fold_part[(j * NCHUNK + chunk) * 64 + o] =
                (red[0][o] + red[1][o]) + (red[2][o] + red[3][o]);
        return;
    }
    int idx = (blockIdx.x - FOLD_BLKS) * 256 + threadIdx.x;
    if (idx < B0) {
        int l = idx >> 13, r = idx & 8191;
        int pos = r & 15, lane = (r >> 4) & 31, t2 = r >> 9;
        int nc = t2 & 3, ks = t2 >> 2;
        int sw = (lane >> 1) & 3;
        int c = (pos >> 2) ^ sw;
        int jw = pos & 3;
        int g = lane >> 2, cc = lane & 3;
        int kp = ks * 8 + cc + ((c >= 2) ? 4 : 0);
        int nt = (c & 1) * 4 + jw;
        int n = nc * 64 + nt * 8 + g;
        const float* src = ipw + l * 16384 + kp * 512 + n;
        u32 h, lo; bfsplit(make_float2(src[0], src[256]), h, lo);
        g_blob[l].ipwPh[r] = h;
        g_blob[l].ipwPl[r] = lo;
    } else if (idx < B1) {
        int j2 = idx - B0, l = j2 >> 12, r = j2 & 4095;
        int jw = r & 3, lane = (r >> 2) & 31, t2 = r >> 7;
        int nc = t2 & 3, ks = t2 >> 2;
        int g = lane >> 2, cc = lane & 3;
        int kp = ks * 8 + cc + ((jw >= 2) ? 4 : 0);
        int nt = jw & 1;
        int n = nc * 16 + nt * 8 + g;
        const float* src = opw + l * 8192 + kp * 128 + n;
        u32 h, lo; bfsplit(make_float2(src[0], src[64]), h, lo);
        g_blob[l].opwPh[r] = h;
        g_blob[l].opwPl[r] = lo;
    } else if (idx < B2) {
        int j2 = idx - B1, l = j2 / 2560, r = j2 - l * 2560;
        int e = r & 1, lane = (r >> 1) & 31, t2 = r >> 6;
        int nt = t2 % 5, ks = t2 / 5;
        int g = lane >> 2, cc = lane & 3;
        int kp = ks * 8 + cc + (e ? 4 : 0);
        int n = nt * 8 + g;
        const float* src = xpw + l * 4608 + (2 * kp) * 36 + n;
        u32 h, lo; bfsplit(make_float2(src[0], src[36]), h, lo);
        g_blob[l].xpjPh[r] = h;
        g_blob[l].xpjPl[r] = lo;
    } else if (idx < B3) {
        int j = idx - B2, l = j >> 9, r = j & 511;
        g_blob[l].dtw[r] = dtw[l * 512 + r];
    } else if (idx < B4) {
        int j = idx - B3, l = j >> 7, r = j & 127;
        g_blob[l].cw3[r] = cw[(l * 128 + r) * 4 + 3];
    } else if (idx < B5) {
        int j = idx - B4, l = j >> 7, r = j & 127;
        g_blob[l].cb[r] = cb[l * 128 + r];
    } else if (idx < B6) {
        int j = idx - B5, l = j >> 7, r = j & 127;
        g_blob[l].dtb[r] = dtb[l * 128 + r];
    } else if (idx < B7) {
        int j = idx - B6, l = j >> 7, r = j & 127;
        g_blob[l].dskip[r] = dskip[l * 128 + r];
    } else if (idx < B8) {
        int j = idx - B7, l = j >> 6, r = j & 63;
        g_blob[l].lng[r] = lng[l * 64 + r];
    } else if (idx < B9) {
        int j = idx - B8, l = j >> 6, r = j & 63;
        g_blob[l].lnb[r] = lnb[l * 64 + r];
    }
}

// ---------------- shared memory (226,816 B; 1 block/SM) ----------------
struct __align__(16) Smem {
    LayerBlob blob;
    u32 xsh[64 * XH_S];       // split residual hi (permuted posA); proj scratch A..D
    u32 xsl[64 * XH_S];
    float xs[64 * XS_S];      // residual fp32
    float xc[64 * XC_S];      // split xc/y halves, permuted pos64 (hi +0, lo +64)
    float sz[64 * XC_S];      // silu(z), then O (fp32, unpermuted)
};

__global__ void __launch_bounds__(THREADS, 1)
mamba_main(const float* __restrict__ xin,
           const float* __restrict__ b_in_nr, const float* __restrict__ b_in_r,
           const float* __restrict__ hw1, const float* __restrict__ hb1,
           const float* __restrict__ hw2, const float* __restrict__ hb2,
           float* __restrict__ out) {
    extern __shared__ __align__(16) char smem_raw[];
    Smem& s = *reinterpret_cast<Smem*>(smem_raw);

    const int t = threadIdx.x;
    const int w = t >> 5;
    const int lane = t & 31;
    const int q = w & 3;
    const int nc = w >> 2;
    const int g = lane >> 2;
    const int cc = lane & 3;
    const int sw = (lane >> 1) & 3;
    const int rb4 = 16 * q + 4 * nc;
    const int pA = posA(lane);
    float* proj = (float*)s.xsh;

    // ---- fold-reduce into SMEM (union'd into xc region) ----
    float* Wnr_s = s.xc;
    float* Wr_s  = s.xc + 768;
    float* bnr_s = s.xc + 1024;
    float* br_s  = s.xc + 1088;
    for (int i = t; i < 1152; i += THREADS) {
        int j = i >> 6, o = i & 63;
        const float* p = g_fold_part + (j * NCHUNK) * 64 + o;
        float a = 0.0f;
#pragma unroll
        for (int k = 0; k < NCHUNK; k++) a += p[k * 64];
        if (j < 12)       Wnr_s[j * 64 + o] = a;
        else if (j == 12) bnr_s[o] = a + b_in_nr[o];
        else if (j < 17)  Wr_s[(j - 13) * 64 + o] = a;
        else              br_s[o] = a + b_in_r[o];
    }
    __syncthreads();

    // ---- x0 = feat @ W_eff + b_eff ----
    {
        const int e0 = blockIdx.x * EPB + 2 * w;
        float fe[2][16];
#pragma unroll
        for (int e = 0; e < 2; e++) {
            const float4* xp = (const float4*)(xin + (size_t)(e0 + e) * 16);
#pragma unroll
            for (int qq = 0; qq < 4; qq++) {
                float4 v = xp[qq];
                fe[e][4 * qq + 0] = v.x; fe[e][4 * qq + 1] = v.y;
                fe[e][4 * qq + 2] = v.z; fe[e][4 * qq + 3] = v.w;
            }
        }
        float2 bn = *(const float2*)&bnr_s[2 * lane];
        float2 bb = *(const float2*)&br_s[2 * lane];
        ull a0 = pk2(bn.x, bn.y), a2 = a0;
        ull a1 = pk2(bb.x, bb.y), a3 = a1;
#pragma unroll
        for (int f = 0; f < 12; f++) {
            ull wp = *(const ull*)&Wnr_s[f * 64 + 2 * lane];
            a0 = ffma2(wp, pk2(fe[0][f], fe[0][f]), a0);
            a2 = ffma2(wp, pk2(fe[1][f], fe[1][f]), a2);
        }
#pragma unroll
        for (int f = 0; f < 4; f++) {
            ull wp = *(const ull*)&Wr_s[f * 64 + 2 * lane];
            a1 = ffma2(wp, pk2(fe[0][12 + f], fe[0][12 + f]), a1);
            a3 = ffma2(wp, pk2(fe[1][12 + f], fe[1][12 + f]), a3);
        }
        ull accs[4] = {a0, a1, a2, a3};
#pragma unroll
        for (int j = 0; j < 4; j++) {
            float v0, v1; upk2(accs[j], v0, v1);
            int row = 4 * w + j;
            *(float2*)&s.xs[row * XS_S + 2 * lane] = make_float2(v0, v1);
            u32 h, lo; bfsplit(make_float2(v0, v1), h, lo);
            s.xsh[row * XH_S + pA] = h;
            s.xsl[row * XH_S + pA] = lo;
        }
    }

    // ================= layer loop =================
#pragma unroll 1
    for (int l = 0; l < NL; l++) {
        __syncthreads();
        {   // blob staging via cp.async (layout-identical flat copy)
            const uint4* src = (const uint4*)&g_blob[l];
            u32 dstb = (u32)__cvta_generic_to_shared(&s.blob);
            for (int i = t; i < BLOB_V4; i += THREADS)
                CP_ASYNC16(dstb + i * 16, src + i);
            CP_COMMIT();
            CP_WAIT0();
        }
        __syncthreads();

        // ======== stage A: xz GEMM; A frags 8x LDS.128, B via swizzled LDS.128 ========
        {
            const int row0 = 16 * q + g, row8 = row0 + 8;
            u32 Xh0[8], Xh8[8], Xl0[8], Xl8[8];
            {
                const u32* p0 = &s.xsh[row0 * XH_S + cc * 8];
                const u32* p8 = &s.xsh[row8 * XH_S + cc * 8];
                const u32* r0 = &s.xsl[row0 * XH_S + cc * 8];
                const u32* r8 = &s.xsl[row8 * XH_S + cc * 8];
                *(uint4*)&Xh0[0] = *(const uint4*)&p0[0];
                *(uint4*)&Xh0[4] = *(const uint4*)&p0[4];
                *(uint4*)&Xh8[0] = *(const uint4*)&p8[0];
                *(uint4*)&Xh8[4] = *(const uint4*)&p8[4];
                *(uint4*)&Xl0[0] = *(const uint4*)&r0[0];
                *(uint4*)&Xl0[4] = *(const uint4*)&r0[4];
                *(uint4*)&Xl8[0] = *(const uint4*)&r8[0];
                *(uint4*)&Xl8[4] = *(const uint4*)&r8[4];
            }
            float acc[8][4];
#pragma unroll
            for (int nt = 0; nt < 8; nt++)
#pragma unroll
                for (int i = 0; i < 4; i++) acc[nt][i] = 0.0f;
#pragma unroll
            for (int ks = 0; ks < 4; ks++) {
                u32 ah[4], al[4];
                ah[0] = Xh0[2 * ks]; ah[1] = Xh8[2 * ks];
                ah[2] = Xh0[2 * ks + 1]; ah[3] = Xh8[2 * ks + 1];
                al[0] = Xl0[2 * ks]; al[1] = Xl8[2 * ks];
                al[2] = Xl0[2 * ks + 1]; al[3] = Xl8[2 * ks + 1];
                const u32* bp_h = &s.blob.ipwPh[(((ks * 4 + nc) * 32) + lane) * 16];
                const u32* bp_l = &s.blob.ipwPl[(((ks * 4 + nc) * 32) + lane) * 16];
                uint4 H0 = *(const uint4*)&bp_h[(0 ^ sw) * 4];
                uint4 H1 = *(const uint4*)&bp_h[(1 ^ sw) * 4];
                uint4 H2 = *(const uint4*)&bp_h[(2 ^ sw) * 4];
                uint4 H3 = *(const uint4*)&bp_h[(3 ^ sw) * 4];
#pragma unroll
                for (int nt = 0; nt < 8; nt++) {
                    u32 b0 = nt < 4 ? uget(H0, nt) : uget(H1, nt - 4);
                    u32 b1 = nt < 4 ? uget(H2, nt) : uget(H3, nt - 4);
                    mma_bf16(acc[nt], ah, b0, b1);
                    mma_bf16(acc[nt], al, b0, b1);
                }
                uint4 L0 = *(const uint4*)&bp_l[(0 ^ sw) * 4];
                uint4 L1 = *(const uint4*)&bp_l[(1 ^ sw) * 4];
                uint4 L2 = *(const uint4*)&bp_l[(2 ^ sw) * 4];
                uint4 L3 = *(const uint4*)&bp_l[(3 ^ sw) * 4];
#pragma unroll
                for (int nt = 0; nt < 8; nt++) {
                    u32 b0 = nt < 4 ? uget(L0, nt) : uget(L1, nt - 4);
                    u32 b1 = nt < 4 ? uget(L2, nt) : uget(L3, nt - 4);
                    mma_bf16(acc[nt], ah, b0, b1);
                }
            }
            if (nc < 2) {        // xc half: conv+silu, stored split in permuted layout
                u32 h0a[8], l0a[8], h8a[8], l8a[8];
#pragma unroll
                for (int nt = 0; nt < 8; nt++) {
                    int col = nc * 64 + nt * 8 + 2 * cc;
                    float2 cwv = *(const float2*)&s.blob.cw3[col];
                    float2 cbv = *(const float2*)&s.blob.cb[col];
                    float2 v0 = make_float2(siluf(fmaf(acc[nt][0], cwv.x, cbv.x)),
                                            siluf(fmaf(acc[nt][1], cwv.y, cbv.y)));
                    float2 v8 = make_float2(siluf(fmaf(acc[nt][2], cwv.x, cbv.x)),
                                            siluf(fmaf(acc[nt][3], cwv.y, cbv.y)));
                    bfsplit(v0, h0a[nt], l0a[nt]);
                    bfsplit(v8, h8a[nt], l8a[nt]);
                }
                u32* xr0 = (u32*)&s.xc[row0 * XC_S];
                u32* xr8 = (u32*)&s.xc[row8 * XC_S];
                int o0 = cc * 16 + (((nc * 2 + 0 + 2 * (cc >> 1)) & 3) << 2);
                int o1 = cc * 16 + (((nc * 2 + 1 + 2 * (cc >> 1)) & 3) << 2);
                *(uint4*)&xr0[o0]      = *(uint4*)&h0a[0];
                *(uint4*)&xr0[o1]      = *(uint4*)&h0a[4];
                *(uint4*)&xr0[64 + o0] = *(uint4*)&l0a[0];
                *(uint4*)&xr0[64 + o1] = *(uint4*)&l0a[4];
                *(uint4*)&xr8[o0]      = *(uint4*)&h8a[0];
                *(uint4*)&xr8[o1]      = *(uint4*)&h8a[4];
                *(uint4*)&xr8[64 + o0] = *(uint4*)&l8a[0];
                *(uint4*)&xr8[64 + o1] = *(uint4*)&l8a[4];
            } else {             // z half: silu, fp32 (unchanged)
#pragma unroll
                for (int nt = 0; nt < 8; nt++) {
                    int col = (nc - 2) * 64 + nt * 8 + 2 * cc;
                    *(float2*)&s.sz[row0 * XC_S + col] =
                        make_float2(siluf(acc[nt][0]), siluf(acc[nt][1]));
                    *(float2*)&s.sz[row8 * XC_S + col] =
                        make_float2(siluf(acc[nt][2]), siluf(acc[nt][3]));
                }
            }
        }
        __syncthreads();   // xsh/xsl reads done before proj overwrites

        // ======== proj GEMM: A frags via swizzled LDS.128 chunks ========
        {
            const int ntb = (nc == 0) ? 0 : nc + 1;   // 0,2,3,4
            const int nte = nc + 2;                   // 2,3,4,5
            const int row0 = 16 * q + g, row8 = row0 + 8;
            const u32* yr0 = (const u32*)&s.xc[row0 * XC_S];
            const u32* yr8 = (const u32*)&s.xc[row8 * XC_S];
            float acc[2][4];
#pragma unroll
            for (int nt = 0; nt < 2; nt++)
#pragma unroll
                for (int i = 0; i < 4; i++) acc[nt][i] = 0.0f;
#pragma unroll
            for (int sub = 0; sub < 4; sub++) {
                int off = cc * 16 + (((sub + 2 * (cc >> 1)) & 3) << 2);
                uint4 H0 = *(const uint4*)&yr0[off];
                uint4 H8 = *(const uint4*)&yr8[off];
                uint4 L0 = *(const uint4*)&yr0[64 + off];
                uint4 L8 = *(const uint4*)&yr8[64 + off];
#pragma unroll
                for (int k2 = 0; k2 < 2; k2++) {
                    int ks = sub * 2 + k2;
                    u32 ah[4], al[4];
                    ah[0] = uget(H0, 2 * k2); ah[1] = uget(H8, 2 * k2);
                    ah[2] = uget(H0, 2 * k2 + 1); ah[3] = uget(H8, 2 * k2 + 1);
                    al[0] = uget(L0, 2 * k2); al[1] = uget(L8, 2 * k2);
                    al[2] = uget(L0, 2 * k2 + 1); al[3] = uget(L8, 2 * k2 + 1);
                    for (int nt = ntb; nt < nte; nt++) {
                        int a = nt - ntb;
                        ull hv = *(const ull*)&s.blob.xpjPh[((ks * 5 + nt) * 32 + lane) * 2];
                        ull lv = *(const ull*)&s.blob.xpjPl[((ks * 5 + nt) * 32 + lane) * 2];
                        u32 bh0 = (u32)hv, bh1 = (u32)(hv >> 32);
                        u32 bl0 = (u32)lv, bl1 = (u32)(lv >> 32);
                        mma_bf16(acc[a], ah, bh0, bh1);
                        mma_bf16(acc[a], ah, bl0, bl1);
                        mma_bf16(acc[a], al, bh0, bh1);
                    }
                }
            }
            for (int nt = ntb; nt < nte; nt++) {
                int a = nt - ntb;
                int col = nt * 8 + 2 * cc;
                *(float2*)&proj[row0 * PROJ_S + col] = make_float2(acc[a][0], acc[a][1]);
                *(float2*)&proj[row8 * PROJ_S + col] = make_float2(acc[a][2], acc[a][3]);
            }
        }
        group_bar(q);

        // ======== stage B: dt/BC/y for rows rb4..rb4+3 ========
        {
            const int p0 = pos64(2 * lane);
            const int p1 = pos64(2 * lane + 1);
            float4 pj[4];
#pragma unroll
            for (int j = 0; j < 4; j++)
                pj[j] = *(const float4*)&proj[(rb4 + j) * PROJ_S];
            float bc[4];
            {
                const int j2 = lane >> 4, sidx = lane & 15;
#pragma unroll
                for (int a = 0; a < 2; a++) {
                    const float* pr = &proj[(rb4 + 2 * a + j2) * PROJ_S];
                    float v = pr[4 + sidx] * pr[20 + sidx];
                    v = half_sum(v);
                    bc[2 * a + 0] = __shfl_sync(0xffffffffu, v, 0);
                    bc[2 * a + 1] = __shfl_sync(0xffffffffu, v, 16);
                }
            }
            float dts[4][4];
            {
                float4 dtbv = *(const float4*)&s.blob.dtb[4 * lane];
#pragma unroll
                for (int j = 0; j < 4; j++) {
                    dts[j][0] = dtbv.x; dts[j][1] = dtbv.y;
                    dts[j][2] = dtbv.z; dts[j][3] = dtbv.w;
                }
#pragma unroll
                for (int r = 0; r < 4; r++) {
                    float4 dwv = *(const float4*)&s.blob.dtw[r * 128 + 4 * lane];
#pragma unroll
                    for (int j = 0; j < 4; j++) {
                        float prj = fget(pj[j], r);
                        dts[j][0] = fmaf(prj, dwv.x, dts[j][0]);
                        dts[j][1] = fmaf(prj, dwv.y, dts[j][1]);
                        dts[j][2] = fmaf(prj, dwv.z, dts[j][2]);
                        dts[j][3] = fmaf(prj, dwv.w, dts[j][3]);
                    }
                }
#pragma unroll
                for (int j = 0; j < 4; j++) {
                    dts[j][0] = softplusf(dts[j][0]); dts[j][1] = softplusf(dts[j][1]);
                    dts[j][2] = softplusf(dts[j][2]); dts[j][3] = softplusf(dts[j][3]);
                }
            }
            {
                float4 dskv = *(const float4*)&s.blob.dskip[4 * lane];
#pragma unroll
                for (int j = 0; j < 4; j++) {
                    u32* xr = (u32*)&s.xc[(rb4 + j) * XC_S];
                    u32 h0w = xr[p0], h1w = xr[p1];
                    u32 l0w = xr[64 + p0], l1w = xr[64 + p1];
                    float xc0 = __uint_as_float(h0w << 16) + __uint_as_float(l0w << 16);
                    float xc1 = __uint_as_float(h0w & 0xffff0000u) + __uint_as_float(l0w & 0xffff0000u);
                    float xc2 = __uint_as_float(h1w << 16) + __uint_as_float(l1w << 16);
                    float xc3 = __uint_as_float(h1w & 0xffff0000u) + __uint_as_float(l1w & 0xffff0000u);
                    float4 szv = *(const float4*)&s.sz[(rb4 + j) * XC_S + 4 * lane];
                    float4 yv;
                    yv.x = xc0 * fmaf(dts[j][0], bc[j], dskv.x) * szv.x;
                    yv.y = xc1 * fmaf(dts[j][1], bc[j], dskv.y) * szv.y;
                    yv.z = xc2 * fmaf(dts[j][2], bc[j], dskv.z) * szv.z;
                    yv.w = xc3 * fmaf(dts[j][3], bc[j], dskv.w) * szv.w;
                    u32 h0, l0, h1, l1;
                    bfsplit(make_float2(yv.x, yv.y), h0, l0);
                    bfsplit(make_float2(yv.z, yv.w), h1, l1);
                    xr[p0] = h0; xr[p1] = h1;
                    xr[64 + p0] = l0; xr[64 + p1] = l1;
                }
            }
        }
        group_bar(q);

        // ======== stage C: out-proj GEMM; A frags via swizzled LDS.128 chunks ========
        {
            const int row0 = 16 * q + g, row8 = row0 + 8;
            const u32* yr0 = (const u32*)&s.xc[row0 * XC_S];
            const u32* yr8 = (const u32*)&s.xc[row8 * XC_S];
            float acc[2][4];
#pragma unroll
            for (int nt = 0; nt < 2; nt++)
#pragma unroll
                for (int i = 0; i < 4; i++) acc[nt][i] = 0.0f;
#pragma unroll
            for (int sub = 0; sub < 4; sub++) {
                int off = cc * 16 + (((sub + 2 * (cc >> 1)) & 3) << 2);
                uint4 H0 = *(const uint4*)&yr0[off];
                uint4 H8 = *(const uint4*)&yr8[off];
                uint4 L0 = *(const uint4*)&yr0[64 + off];
                uint4 L8 = *(const uint4*)&yr8[64 + off];
#pragma unroll
                for (int k2 = 0; k2 < 2; k2++) {
                    int ks = sub * 2 + k2;
                    u32 ah[4], al[4];
                    ah[0] = uget(H0, 2 * k2); ah[1] = uget(H8, 2 * k2);
                    ah[2] = uget(H0, 2 * k2 + 1); ah[3] = uget(H8, 2 * k2 + 1);
                    al[0] = uget(L0, 2 * k2); al[1] = uget(L8, 2 * k2);
                    al[2] = uget(L0, 2 * k2 + 1); al[3] = uget(L8, 2 * k2 + 1);
                    uint4 UH = *(const uint4*)&s.blob.opwPh[(((ks * 4 + nc) * 32) + lane) * 4];
                    uint4 UL = *(const uint4*)&s.blob.opwPl[(((ks * 4 + nc) * 32) + lane) * 4];
                    mma_bf16(acc[0], ah, UH.x, UH.z);
                    mma_bf16(acc[0], ah, UL.x, UL.z);
                    mma_bf16(acc[0], al, UH.x, UH.z);
                    mma_bf16(acc[1], ah, UH.y, UH.w);
                    mma_bf16(acc[1], ah, UL.y, UL.w);
                    mma_bf16(acc[1], al, UH.y, UH.w);
                }
            }
#pragma unroll
            for (int nt = 0; nt < 2; nt++) {
                int col = nc * 16 + nt * 8 + 2 * cc;
                *(float2*)&s.sz[row0 * XC_S + col] = make_float2(acc[nt][0], acc[nt][1]);
                *(float2*)&s.sz[row8 * XC_S + col] = make_float2(acc[nt][2], acc[nt][3]);
            }
        }
        __syncthreads();   // proj reads done before stage D rewrites xsh/xsl

        // ======== stage D: layernorm(64) + residual; write fp32 + permuted split ========
        {
            float2 gv = *(const float2*)&s.blob.lng[2 * lane];
            float2 bv = *(const float2*)&s.blob.lnb[2 * lane];
#pragma unroll
            for (int j = 0; j < 4; j++) {
                int row = rb4 + j;
                float2 ov = *(const float2*)&s.sz[row * XC_S + 2 * lane];
                float m  = warp_sum(ov.x + ov.y) * (1.0f / 64.0f);
                float m2 = warp_sum(ov.x * ov.x + ov.y * ov.y) * (1.0f / 64.0f);
                float rs = rsqrtf(m2 - m * m + EPSV);
                float2 xv = *(const float2*)&s.xs[row * XS_S + 2 * lane];
                xv.x += (ov.x - m) * rs * gv.x + bv.x;
                xv.y += (ov.y - m) * rs * gv.y + bv.y;
                *(float2*)&s.xs[row * XS_S + 2 * lane] = xv;
                u32 h, lo; bfsplit(xv, h, lo);
                s.xsh[row * XH_S + pA] = h;
                s.xsl[row * XH_S + pA] = lo;
            }
        }
    }

    // ================= head =================
    __syncthreads();
    {
        float* hs = s.xc;   // reuse as hw1[128][33]
        for (int i = t; i < 4096; i += THREADS) {
            int k = i >> 5, c = i & 31;
            hs[k * 33 + c] = hw1[i];
        }
        float* hb1s = s.sz;
        float* hw2s = s.sz + 64;
        if (t < 32) { hb1s[t] = hb1[t]; hw2s[t] = hw2[t]; }
        __syncthreads();

        float b2v = hb2[0];
#pragma unroll
        for (int j = 0; j < 2; j++) {
            int ra = 4 * w + 2 * j;
            float h = hb1s[lane];
            const float* xa = &s.xs[ra * XS_S];
            const float* xb = &s.xs[(ra + 1) * XS_S];
#pragma unroll 8
            for (int k = 0; k < 64; k++) h = fmaf(xa[k], hs[k * 33 + lane], h);
#pragma unroll 8
            for (int k = 0; k < 64; k++) h = fmaf(xb[k], hs[(64 + k) * 33 + lane], h);
            h = fmaxf(h, 0.0f);
            float v = warp_sum(h * hw2s[lane]);
            if (lane == 0) out[blockIdx.x * EPB + 2 * w + j] = v + b2v;
        }
    }
}

extern "C" void kernel_launch(void* const* d_in, const int* in_sizes, int n_in,
                              void* d_out, int out_size) {
    const float* x        = (const float*)d_in[0];
    const float* w_nr     = (const float*)d_in[1];
    const float* b_nr     = (const float*)d_in[2];
    const float* w_r      = (const float*)d_in[3];
    const float* b_r      = (const float*)d_in[4];
    const float* w_in_nr  = (const float*)d_in[5];
    const float* b_in_nr  = (const float*)d_in[6];
    const float* w_in_r   = (const float*)d_in[7];
    const float* b_in_r   = (const float*)d_in[8];
    const float* ipw      = (const float*)d_in[9];
    const float* cw       = (const float*)d_in[10];
    const float* cb       = (const float*)d_in[11];
    const float* xpw      = (const float*)d_in[12];
    const float* dtw      = (const float*)d_in[13];
    const float* dtb      = (const float*)d_in[14];
    /* alog d_in[15] dead at L=1 (scan h0=0) */
    const float* dskip    = (const float*)d_in[16];
    const float* opw      = (const float*)d_in[17];
    const float* lng      = (const float*)d_in[18];
    const float* lnb      = (const float*)d_in[19];
    const float* hw1      = (const float*)d_in[20];
    const float* hb1      = (const float*)d_in[21];
    const float* hw2      = (const float*)d_in[22];
    const float* hb2      = (const float*)d_in[23];

    size_t smem = sizeof(Smem);
    cudaFuncSetAttribute((const void*)mamba_main,
                         cudaFuncAttributeMaxDynamicSharedMemorySize, (int)smem);

    prep_all<<<FOLD_BLKS + BLOB_BLKS, 256>>>(w_nr, b_nr, w_r, b_r, w_in_nr, w_in_r,
                                             ipw, opw, xpw, dtw, cw, cb, dtb, dskip,
                                             lng, lnb);
    mamba_main<<<NBLK, THREADS, smem>>>(x, b_in_nr, b_in_r, hw1, hb1, hw2, hb2,
                                        (float*)d_out);
}

// round 14
// speedup vs baseline: 1.1935x; 1.1935x over previous
#include <cuda_runtime.h>

#define NL 4
#define BATCH 16384
#define THREADS 256
#define EPB 16
#define NBLK (BATCH / EPB)       // 1024 blocks, 2 per SM
#define XS_S 68
#define XC_S 132
#define XH_S 36
#define PROJ_S 72
#define NCHUNK 16
#define EPSV 1e-5f

typedef unsigned long long ull;
typedef unsigned int u32;

__device__ __forceinline__ ull pk2(float lo, float hi) {
    ull r; asm("mov.b64 %0,{%1,%2};" : "=l"(r) : "f"(lo), "f"(hi)); return r;
}
__device__ __forceinline__ void upk2(ull v, float& lo, float& hi) {
    asm("mov.b64 {%0,%1},%2;" : "=f"(lo), "=f"(hi) : "l"(v));
}
__device__ __forceinline__ ull ffma2(ull a, ull b, ull c) {
    ull d; asm("fma.rn.f32x2 %0,%1,%2,%3;" : "=l"(d) : "l"(a), "l"(b), "l"(c)); return d;
}
__device__ __forceinline__ float warp_sum(float v) {
    v += __shfl_xor_sync(0xffffffffu, v, 16);
    v += __shfl_xor_sync(0xffffffffu, v, 8);
    v += __shfl_xor_sync(0xffffffffu, v, 4);
    v += __shfl_xor_sync(0xffffffffu, v, 2);
    v += __shfl_xor_sync(0xffffffffu, v, 1);
    return v;
}
__device__ __forceinline__ float half_sum(float v) {
    v += __shfl_xor_sync(0xffffffffu, v, 8);
    v += __shfl_xor_sync(0xffffffffu, v, 4);
    v += __shfl_xor_sync(0xffffffffu, v, 2);
    v += __shfl_xor_sync(0xffffffffu, v, 1);
    return v;
}
__device__ __forceinline__ void group_bar(int q) {
    asm volatile("bar.sync %0, 128;" :: "r"(q + 1) : "memory");
}
__device__ __forceinline__ float siluf(float v) {
    return __fdividef(v, 1.0f + __expf(-v));
}
__device__ __forceinline__ float softplusf(float v) {
    return fmaxf(v, 0.0f) + __logf(1.0f + __expf(-fabsf(v)));
}
__device__ __forceinline__ float fget(float4 v, int r) {
    return r == 0 ? v.x : r == 1 ? v.y : r == 2 ? v.z : v.w;
}
__device__ __forceinline__ u32 uget(uint4 v, int r) {
    return r == 0 ? v.x : r == 1 ? v.y : r == 2 ? v.z : v.w;
}
__device__ __forceinline__ void bfsplit(float2 p, u32& h, u32& l) {
    asm("cvt.rn.satfinite.bf16x2.f32 %0,%1,%2;" : "=r"(h) : "f"(p.y), "f"(p.x));
    float h0 = __uint_as_float(h << 16);
    float h1 = __uint_as_float(h & 0xffff0000u);
    asm("cvt.rn.satfinite.bf16x2.f32 %0,%1,%2;" : "=r"(l) : "f"(p.y - h1), "f"(p.x - h0));
}
__device__ __forceinline__ void mma_bf16(float* c, const u32* a, u32 b0, u32 b1) {
    asm("mma.sync.aligned.m16n8k16.row.col.f32.bf16.bf16.f32 "
        "{%0,%1,%2,%3},{%4,%5,%6,%7},{%8,%9},{%0,%1,%2,%3};"
        : "+f"(c[0]), "+f"(c[1]), "+f"(c[2]), "+f"(c[3])
        : "r"(a[0]), "r"(a[1]), "r"(a[2]), "r"(a[3]), "r"(b0), "r"(b1));
}

// ---------- per-layer weight blob: fragment-order packing (L2-resident) ----------
struct __align__(16) LayerBlob {
    u32 ipwPh[4 * 4 * 32 * 16];
    u32 ipwPl[4 * 4 * 32 * 16];
    u32 opwPh[8 * 4 * 32 * 4];
    u32 opwPl[8 * 4 * 32 * 4];
    u32 xpjPh[8 * 5 * 32 * 2];
    u32 xpjPl[8 * 5 * 32 * 2];
    float dtw[4 * 128];
    float cw3[128];
    float cb[128];
    float dtb[128];
    float dskip[128];
    float lng[64];
    float lnb[64];
};

__device__ LayerBlob g_blob[NL];
__device__ float g_fold_part[18 * NCHUNK * 64];

#define FOLD_BLKS (18 * NCHUNK)
#define B0 (NL * 8192)
#define B1 (B0 + NL * 4096)
#define B2 (B1 + NL * 2560)
#define B3 (B2 + NL * 512)
#define B4 (B3 + NL * 128)
#define B5 (B4 + NL * 128)
#define B6 (B5 + NL * 128)
#define B7 (B6 + NL * 128)
#define B8 (B7 + NL * 64)
#define B9 (B8 + NL * 64)
#define BLOB_BLKS ((B9 + 255) / 256)

__global__ void __launch_bounds__(256)
prep_all(const float* __restrict__ w_nr, const float* __restrict__ b_nr,
         const float* __restrict__ w_r,  const float* __restrict__ b_r,
         const float* __restrict__ w_in_nr, const float* __restrict__ w_in_r,
         const float* __restrict__ ipw, const float* __restrict__ opw,
         const float* __restrict__ xpw, const float* __restrict__ dtw,
         const float* __restrict__ cw,  const float* __restrict__ cb,
         const float* __restrict__ dtb, const float* __restrict__ dskip,
         const float* __restrict__ lng, const float* __restrict__ lnb) {
    if (blockIdx.x < FOLD_BLKS) {
        __shared__ float red[4][64];
        const int j = blockIdx.x / NCHUNK;
        const int chunk = blockIdx.x - j * NCHUNK;
        const int o = threadIdx.x & 63;
        const int cg = threadIdx.x >> 6;
        const float* vec;
        const float* mat;
        if (j < 12)       { vec = w_nr + j * 1000;        mat = w_in_nr; }
        else if (j == 12) { vec = b_nr;                   mat = w_in_nr; }
        else if (j < 17)  { vec = w_r + (j - 13) * 1000;  mat = w_in_r;  }
        else              { vec = b_r;                    mat = w_in_r;  }
        const int cbase = chunk * 63;
        const int cend = (cbase + 63 < 1000) ? cbase + 63 : 1000;
        float a0 = 0.f, a1 = 0.f;
        for (int c = cbase + cg * 2; c < cend; c += 8) {
            a0 = fmaf(vec[c], mat[c * 64 + o], a0);
            if (c + 1 < cend)
                a1 = fmaf(vec[c + 1], mat[(c + 1) * 64 + o], a1);
        }
        red[cg][o] = a0 + a1;
        __syncthreads();
        if (cg == 0)
            g_fold_part[(j * NCHUNK + chunk) * 64 + o] =
                (red[0][o] + red[1][o]) + (red[2][o] + red[3][o]);
        return;
    }
    int idx = (blockIdx.x - FOLD_BLKS) * 256 + threadIdx.x;
    if (idx < B0) {
        int l = idx >> 13, r = idx & 8191;
        int pos = r & 15, lane = (r >> 4) & 31, t2 = r >> 9;
        int nc = t2 & 3, ks = t2 >> 2;
        int sw = (lane >> 1) & 3;
        int c = (pos >> 2) ^ sw;
        int jw = pos & 3;
        int g = lane >> 2, cc = lane & 3;
        int kp = ks * 8 + cc + ((c >= 2) ? 4 : 0);
        int nt = (c & 1) * 4 + jw;
        int n = nc * 64 + nt * 8 + g;
        const float* src = ipw + l * 16384 + kp * 512 + n;
        u32 h, lo; bfsplit(make_float2(src[0], src[256]), h, lo);
        g_blob[l].ipwPh[r] = h;
        g_blob[l].ipwPl[r] = lo;
    } else if (idx < B1) {
        int j2 = idx - B0, l = j2 >> 12, r = j2 & 4095;
        int jw = r & 3, lane = (r >> 2) & 31, t2 = r >> 7;
        int nc = t2 & 3, ks = t2 >> 2;
        int g = lane >> 2, cc = lane & 3;
        int kp = ks * 8 + cc + ((jw >= 2) ? 4 : 0);
        int nt = jw & 1;
        int n = nc * 16 + nt * 8 + g;
        const float* src = opw + l * 8192 + kp * 128 + n;
        u32 h, lo; bfsplit(make_float2(src[0], src[64]), h, lo);
        g_blob[l].opwPh[r] = h;
        g_blob[l].opwPl[r] = lo;
    } else if (idx < B2) {
        int j2 = idx - B1, l = j2 / 2560, r = j2 - l * 2560;
        int e = r & 1, lane = (r >> 1) & 31, t2 = r >> 6;
        int nt = t2 % 5, ks = t2 / 5;
        int g = lane >> 2, cc = lane & 3;
        int kp = ks * 8 + cc + (e ? 4 : 0);
        int n = nt * 8 + g;
        const float* src = xpw + l * 4608 + (2 * kp) * 36 + n;
        u32 h, lo; bfsplit(make_float2(src[0], src[36]), h, lo);
        g_blob[l].xpjPh[r] = h;
        g_blob[l].xpjPl[r] = lo;
    } else if (idx < B3) {
        int j = idx - B2, l = j >> 9, r = j & 511;
        g_blob[l].dtw[r] = dtw[l * 512 + r];
    } else if (idx < B4) {
        int j = idx - B3, l = j >> 7, r = j & 127;
        g_blob[l].cw3[r] = cw[(l * 128 + r) * 4 + 3];
    } else if (idx < B5) {
        int j = idx - B4, l = j >> 7, r = j & 127;
        g_blob[l].cb[r] = cb[l * 128 + r];
    } else if (idx < B6) {
        int j = idx - B5, l = j >> 7, r = j & 127;
        g_blob[l].dtb[r] = dtb[l * 128 + r];
    } else if (idx < B7) {
        int j = idx - B6, l = j >> 7, r = j & 127;
        g_blob[l].dskip[r] = dskip[l * 128 + r];
    } else if (idx < B8) {
        int j = idx - B7, l = j >> 6, r = j & 63;
        g_blob[l].lng[r] = lng[l * 64 + r];
    } else if (idx < B9) {
        int j = idx - B8, l = j >> 6, r = j & 63;
        g_blob[l].lnb[r] = lnb[l * 64 + r];
    }
}

// ---------------- shared memory (51,712 B; 2 blocks/SM) ----------------
struct __align__(16) Smem {
    u32 xsh[32 * XH_S];       // split residual hi; proj scratch between A and D
    u32 xsl[32 * XH_S];       // proj[32][72] overlays xsh+xsl exactly
    float xs[32 * XS_S];      // residual fp32
    float xc[32 * XC_S];      // split xc/y (hi cols 0..63, lo 64..127); init + head scratch
    float sz[32 * XC_S];      // silu(z), then O
};

__global__ void __launch_bounds__(THREADS, 2)
mamba_main(const float* __restrict__ xin,
           const float* __restrict__ b_in_nr, const float* __restrict__ b_in_r,
           const float* __restrict__ hw1, const float* __restrict__ hb1,
           const float* __restrict__ hw2, const float* __restrict__ hb2,
           float* __restrict__ out) {
    extern __shared__ __align__(16) char smem_raw[];
    Smem& s = *reinterpret_cast<Smem*>(smem_raw);

    const int t = threadIdx.x;
    const int w = t >> 5;          // 0..7
    const int lane = t & 31;
    const int q = w & 1;           // m-tile / barrier group (2 groups of 4 warps)
    const int nc = w >> 1;         // n-chunk 0..3
    const int g = lane >> 2;
    const int cc = lane & 3;
    const int sw = (lane >> 1) & 3;
    const int rb4 = 16 * q + 4 * nc;
    float* proj = (float*)s.xsh;   // proj[32][72] = 2304 floats = xsh+xsl

    // ---- fold-reduce into SMEM (union'd into xc region) ----
    float* Wnr_s = s.xc;
    float* Wr_s  = s.xc + 768;
    float* bnr_s = s.xc + 1024;
    float* br_s  = s.xc + 1088;
    for (int i = t; i < 1152; i += THREADS) {
        int j = i >> 6, o = i & 63;
        const float* p = g_fold_part + (j * NCHUNK) * 64 + o;
        float a = 0.0f;
#pragma unroll
        for (int k = 0; k < NCHUNK; k++) a += p[k * 64];
        if (j < 12)       Wnr_s[j * 64 + o] = a;
        else if (j == 12) bnr_s[o] = a + b_in_nr[o];
        else if (j < 17)  Wr_s[(j - 13) * 64 + o] = a;
        else              br_s[o] = a + b_in_r[o];
    }
    __syncthreads();

    // ---- x0 = feat @ W_eff + b_eff : warp w -> rows 4w..4w+3 ----
    {
        const int e0 = blockIdx.x * EPB + 2 * w;
        float fe[2][16];
#pragma unroll
        for (int e = 0; e < 2; e++) {
            const float4* xp = (const float4*)(xin + (size_t)(e0 + e) * 16);
#pragma unroll
            for (int qq = 0; qq < 4; qq++) {
                float4 v = xp[qq];
                fe[e][4 * qq + 0] = v.x; fe[e][4 * qq + 1] = v.y;
                fe[e][4 * qq + 2] = v.z; fe[e][4 * qq + 3] = v.w;
            }
        }
        float2 bn = *(const float2*)&bnr_s[2 * lane];
        float2 bb = *(const float2*)&br_s[2 * lane];
        ull a0 = pk2(bn.x, bn.y), a2 = a0;
        ull a1 = pk2(bb.x, bb.y), a3 = a1;
#pragma unroll
        for (int f = 0; f < 12; f++) {
            ull wp = *(const ull*)&Wnr_s[f * 64 + 2 * lane];
            a0 = ffma2(wp, pk2(fe[0][f], fe[0][f]), a0);
            a2 = ffma2(wp, pk2(fe[1][f], fe[1][f]), a2);
        }
#pragma unroll
        for (int f = 0; f < 4; f++) {
            ull wp = *(const ull*)&Wr_s[f * 64 + 2 * lane];
            a1 = ffma2(wp, pk2(fe[0][12 + f], fe[0][12 + f]), a1);
            a3 = ffma2(wp, pk2(fe[1][12 + f], fe[1][12 + f]), a3);
        }
        ull accs[4] = {a0, a1, a2, a3};
#pragma unroll
        for (int j = 0; j < 4; j++) {
            float v0, v1; upk2(accs[j], v0, v1);
            int row = 4 * w + j;
            *(float2*)&s.xs[row * XS_S + 2 * lane] = make_float2(v0, v1);
            u32 h, lo; bfsplit(make_float2(v0, v1), h, lo);
            s.xsh[row * XH_S + lane] = h;
            s.xsl[row * XH_S + lane] = lo;
        }
    }

    // ================= layer loop (weights served from L2) =================
#pragma unroll 1
    for (int l = 0; l < NL; l++) {
        const LayerBlob* __restrict__ gb = &g_blob[l];
        __syncthreads();   // stage D / init writes visible to all of stage A

        // ======== stage A: xz GEMM; B frags via LDG.128 from L2 ========
        {
            const int row0 = 16 * q + g, row8 = row0 + 8;
            const u32* xh0 = &s.xsh[row0 * XH_S];
            const u32* xh8 = &s.xsh[row8 * XH_S];
            const u32* xl0 = &s.xsl[row0 * XH_S];
            const u32* xl8 = &s.xsl[row8 * XH_S];
            float acc[8][4];
#pragma unroll
            for (int nt = 0; nt < 8; nt++)
#pragma unroll
                for (int i = 0; i < 4; i++) acc[nt][i] = 0.0f;
#pragma unroll
            for (int ks = 0; ks < 4; ks++) {
                const int kp = ks * 8 + cc;
                u32 ah[4], al[4];
                ah[0] = xh0[kp];     ah[1] = xh8[kp];
                ah[2] = xh0[kp + 4]; ah[3] = xh8[kp + 4];
                al[0] = xl0[kp];     al[1] = xl8[kp];
                al[2] = xl0[kp + 4]; al[3] = xl8[kp + 4];
                const uint4* bp_h = (const uint4*)&gb->ipwPh[(((ks * 4 + nc) * 32) + lane) * 16];
                const uint4* bp_l = (const uint4*)&gb->ipwPl[(((ks * 4 + nc) * 32) + lane) * 16];
                uint4 H0 = __ldg(&bp_h[0 ^ sw]);
                uint4 H1 = __ldg(&bp_h[1 ^ sw]);
                uint4 H2 = __ldg(&bp_h[2 ^ sw]);
                uint4 H3 = __ldg(&bp_h[3 ^ sw]);
                uint4 L0 = __ldg(&bp_l[0 ^ sw]);
                uint4 L1 = __ldg(&bp_l[1 ^ sw]);
                uint4 L2 = __ldg(&bp_l[2 ^ sw]);
                uint4 L3 = __ldg(&bp_l[3 ^ sw]);
#pragma unroll
                for (int nt = 0; nt < 8; nt++) {
                    u32 b0 = nt < 4 ? uget(H0, nt) : uget(H1, nt - 4);
                    u32 b1 = nt < 4 ? uget(H2, nt) : uget(H3, nt - 4);
                    mma_bf16(acc[nt], ah, b0, b1);
                    mma_bf16(acc[nt], al, b0, b1);
                }
#pragma unroll
                for (int nt = 0; nt < 8; nt++) {
                    u32 b0 = nt < 4 ? uget(L0, nt) : uget(L1, nt - 4);
                    u32 b1 = nt < 4 ? uget(L2, nt) : uget(L3, nt - 4);
                    mma_bf16(acc[nt], ah, b0, b1);
                }
            }
            if (nc < 2) {        // xc half: conv tap + silu, stored split
                u32* xr0 = (u32*)&s.xc[row0 * XC_S];
                u32* xr8 = (u32*)&s.xc[row8 * XC_S];
#pragma unroll
                for (int nt = 0; nt < 8; nt++) {
                    int col = nc * 64 + nt * 8 + 2 * cc;
                    int p = col >> 1;
                    float2 cwv = *(const float2*)&gb->cw3[col];
                    float2 cbv = *(const float2*)&gb->cb[col];
                    float2 v0 = make_float2(siluf(fmaf(acc[nt][0], cwv.x, cbv.x)),
                                            siluf(fmaf(acc[nt][1], cwv.y, cbv.y)));
                    float2 v8 = make_float2(siluf(fmaf(acc[nt][2], cwv.x, cbv.x)),
                                            siluf(fmaf(acc[nt][3], cwv.y, cbv.y)));
                    u32 h, lo;
                    bfsplit(v0, h, lo); xr0[p] = h; xr0[64 + p] = lo;
                    bfsplit(v8, h, lo); xr8[p] = h; xr8[64 + p] = lo;
                }
            } else {             // z half: silu, fp32
#pragma unroll
                for (int nt = 0; nt < 8; nt++) {
                    int col = (nc - 2) * 64 + nt * 8 + 2 * cc;
                    *(float2*)&s.sz[row0 * XC_S + col] =
                        make_float2(siluf(acc[nt][0]), siluf(acc[nt][1]));
                    *(float2*)&s.sz[row8 * XC_S + col] =
                        make_float2(siluf(acc[nt][2]), siluf(acc[nt][3]));
                }
            }
        }
        __syncthreads();   // xsh/xsl reads done block-wide before proj overwrites

        // ======== proj GEMM: n-tiles 2/1/1/1; B via LDG.64 ========
        {
            const int ntb = (nc == 0) ? 0 : nc + 1;
            const int nte = nc + 2;
            const int row0 = 16 * q + g, row8 = row0 + 8;
            const u32* yh0 = (const u32*)&s.xc[row0 * XC_S];
            const u32* yh8 = (const u32*)&s.xc[row8 * XC_S];
            float acc[2][4];
#pragma unroll
            for (int nt = 0; nt < 2; nt++)
#pragma unroll
                for (int i = 0; i < 4; i++) acc[nt][i] = 0.0f;
#pragma unroll
            for (int ks = 0; ks < 8; ks++) {
                const int kp = ks * 8 + cc;
                u32 ah[4], al[4];
                ah[0] = yh0[kp];          ah[1] = yh8[kp];
                ah[2] = yh0[kp + 4];      ah[3] = yh8[kp + 4];
                al[0] = yh0[64 + kp];     al[1] = yh8[64 + kp];
                al[2] = yh0[64 + kp + 4]; al[3] = yh8[64 + kp + 4];
                for (int nt = ntb; nt < nte; nt++) {
                    int a = nt - ntb;
                    ull hv = __ldg((const ull*)&gb->xpjPh[((ks * 5 + nt) * 32 + lane) * 2]);
                    ull lv = __ldg((const ull*)&gb->xpjPl[((ks * 5 + nt) * 32 + lane) * 2]);
                    u32 bh0 = (u32)hv, bh1 = (u32)(hv >> 32);
                    u32 bl0 = (u32)lv, bl1 = (u32)(lv >> 32);
                    mma_bf16(acc[a], ah, bh0, bh1);
                    mma_bf16(acc[a], ah, bl0, bl1);
                    mma_bf16(acc[a], al, bh0, bh1);
                }
            }
            for (int nt = ntb; nt < nte; nt++) {
                int a = nt - ntb;
                int col = nt * 8 + 2 * cc;
                *(float2*)&proj[row0 * PROJ_S + col] = make_float2(acc[a][0], acc[a][1]);
                *(float2*)&proj[row8 * PROJ_S + col] = make_float2(acc[a][2], acc[a][3]);
            }
        }
        group_bar(q);

        // ======== stage B: dt/BC/y for rows rb4..rb4+3 ========
        {
            float4 pj[4];
#pragma unroll
            for (int j = 0; j < 4; j++)
                pj[j] = *(const float4*)&proj[(rb4 + j) * PROJ_S];
            float bc[4];
            {
                const int j2 = lane >> 4, sidx = lane & 15;
#pragma unroll
                for (int a = 0; a < 2; a++) {
                    const float* pr = &proj[(rb4 + 2 * a + j2) * PROJ_S];
                    float v = pr[4 + sidx] * pr[20 + sidx];
                    v = half_sum(v);
                    bc[2 * a + 0] = __shfl_sync(0xffffffffu, v, 0);
                    bc[2 * a + 1] = __shfl_sync(0xffffffffu, v, 16);
                }
            }
            float dts[4][4];
            {
                float4 dtbv = __ldg((const float4*)&gb->dtb[4 * lane]);
#pragma unroll
                for (int j = 0; j < 4; j++) {
                    dts[j][0] = dtbv.x; dts[j][1] = dtbv.y;
                    dts[j][2] = dtbv.z; dts[j][3] = dtbv.w;
                }
#pragma unroll
                for (int r = 0; r < 4; r++) {
                    float4 dwv = __ldg((const float4*)&gb->dtw[r * 128 + 4 * lane]);
#pragma unroll
                    for (int j = 0; j < 4; j++) {
                        float prj = fget(pj[j], r);
                        dts[j][0] = fmaf(prj, dwv.x, dts[j][0]);
                        dts[j][1] = fmaf(prj, dwv.y, dts[j][1]);
                        dts[j][2] = fmaf(prj, dwv.z, dts[j][2]);
                        dts[j][3] = fmaf(prj, dwv.w, dts[j][3]);
                    }
                }
#pragma unroll
                for (int j = 0; j < 4; j++) {
                    dts[j][0] = softplusf(dts[j][0]); dts[j][1] = softplusf(dts[j][1]);
                    dts[j][2] = softplusf(dts[j][2]); dts[j][3] = softplusf(dts[j][3]);
                }
            }
            {
                float4 dskv = __ldg((const float4*)&gb->dskip[4 * lane]);
#pragma unroll
                for (int j = 0; j < 4; j++) {
                    u32* xr = (u32*)&s.xc[(rb4 + j) * XC_S];
                    uint2 hh = *(const uint2*)&xr[2 * lane];
                    uint2 ll = *(const uint2*)&xr[64 + 2 * lane];
                    float xc0 = __uint_as_float(hh.x << 16) + __uint_as_float(ll.x << 16);
                    float xc1 = __uint_as_float(hh.x & 0xffff0000u) + __uint_as_float(ll.x & 0xffff0000u);
                    float xc2 = __uint_as_float(hh.y << 16) + __uint_as_float(ll.y << 16);
                    float xc3 = __uint_as_float(hh.y & 0xffff0000u) + __uint_as_float(ll.y & 0xffff0000u);
                    float4 szv = *(const float4*)&s.sz[(rb4 + j) * XC_S + 4 * lane];
                    float4 yv;
                    yv.x = xc0 * fmaf(dts[j][0], bc[j], dskv.x) * szv.x;
                    yv.y = xc1 * fmaf(dts[j][1], bc[j], dskv.y) * szv.y;
                    yv.z = xc2 * fmaf(dts[j][2], bc[j], dskv.z) * szv.z;
                    yv.w = xc3 * fmaf(dts[j][3], bc[j], dskv.w) * szv.w;
                    u32 h0, l0, h1, l1;
                    bfsplit(make_float2(yv.x, yv.y), h0, l0);
                    bfsplit(make_float2(yv.z, yv.w), h1, l1);
                    *(uint2*)&xr[2 * lane]      = make_uint2(h0, h1);
                    *(uint2*)&xr[64 + 2 * lane] = make_uint2(l0, l1);
                }
            }
        }
        group_bar(q);

        // ======== stage C: out-proj GEMM; B via LDG.128 ========
        {
            const int row0 = 16 * q + g, row8 = row0 + 8;
            const u32* yh0 = (const u32*)&s.xc[row0 * XC_S];
            const u32* yh8 = (const u32*)&s.xc[row8 * XC_S];
            float acc[2][4];
#pragma unroll
            for (int nt = 0; nt < 2; nt++)
#pragma unroll
                for (int i = 0; i < 4; i++) acc[nt][i] = 0.0f;
#pragma unroll
            for (int ks = 0; ks < 8; ks++) {
                const int kp = ks * 8 + cc;
                u32 ah[4], al[4];
                ah[0] = yh0[kp];          ah[1] = yh8[kp];
                ah[2] = yh0[kp + 4];      ah[3] = yh8[kp + 4];
                al[0] = yh0[64 + kp];     al[1] = yh8[64 + kp];
                al[2] = yh0[64 + kp + 4]; al[3] = yh8[64 + kp + 4];
                uint4 UH = __ldg((const uint4*)&gb->opwPh[(((ks * 4 + nc) * 32) + lane) * 4]);
                uint4 UL = __ldg((const uint4*)&gb->opwPl[(((ks * 4 + nc) * 32) + lane) * 4]);
                mma_bf16(acc[0], ah, UH.x, UH.z);
                mma_bf16(acc[0], ah, UL.x, UL.z);
                mma_bf16(acc[0], al, UH.x, UH.z);
                mma_bf16(acc[1], ah, UH.y, UH.w);
                mma_bf16(acc[1], ah, UL.y, UL.w);
                mma_bf16(acc[1], al, UH.y, UH.w);
            }
#pragma unroll
            for (int nt = 0; nt < 2; nt++) {
                int col = nc * 16 + nt * 8 + 2 * cc;
                *(float2*)&s.sz[row0 * XC_S + col] = make_float2(acc[nt][0], acc[nt][1]);
                *(float2*)&s.sz[row8 * XC_S + col] = make_float2(acc[nt][2], acc[nt][3]);
            }
        }
        __syncthreads();   // all proj reads done before stage D rewrites xsh/xsl

        // ======== stage D: layernorm(64) + residual; write fp32 + split ========
        {
            float2 gv = __ldg((const float2*)&gb->lng[2 * lane]);
            float2 bv = __ldg((const float2*)&gb->lnb[2 * lane]);
#pragma unroll
            for (int j = 0; j < 4; j++) {
                int row = rb4 + j;
                float2 ov = *(const float2*)&s.sz[row * XC_S + 2 * lane];
                float m  = warp_sum(ov.x + ov.y) * (1.0f / 64.0f);
                float m2 = warp_sum(ov.x * ov.x + ov.y * ov.y) * (1.0f / 64.0f);
                float rs = rsqrtf(m2 - m * m + EPSV);
                float2 xv = *(const float2*)&s.xs[row * XS_S + 2 * lane];
                xv.x += (ov.x - m) * rs * gv.x + bv.x;
                xv.y += (ov.y - m) * rs * gv.y + bv.y;
                *(float2*)&s.xs[row * XS_S + 2 * lane] = xv;
                u32 h, lo; bfsplit(xv, h, lo);
                s.xsh[row * XH_S + lane] = h;
                s.xsl[row * XH_S + lane] = lo;
            }
        }
    }

    // ================= head =================
    __syncthreads();
    {
        float* hs = s.xc;   // reuse as hw1[128][33] = 4224 floats (fits exactly)
        for (int i = t; i < 4096; i += THREADS) {
            int k = i >> 5, c = i & 31;
            hs[k * 33 + c] = hw1[i];
        }
        float* hb1s = s.sz;
        float* hw2s = s.sz + 64;
        if (t < 32) { hb1s[t] = hb1[t]; hw2s[t] = hw2[t]; }
        __syncthreads();

        float b2v = hb2[0];
#pragma unroll
        for (int j = 0; j < 2; j++) {
            int ra = 4 * w + 2 * j;
            float h = hb1s[lane];
            const float* xa = &s.xs[ra * XS_S];
            const float* xb = &s.xs[(ra + 1) * XS_S];
#pragma unroll 8
            for (int k = 0; k < 64; k++) h = fmaf(xa[k], hs[k * 33 + lane], h);
#pragma unroll 8
            for (int k = 0; k < 64; k++) h = fmaf(xb[k], hs[(64 + k) * 33 + lane], h);
            h = fmaxf(h, 0.0f);
            float v = warp_sum(h * hw2s[lane]);
            if (lane == 0) out[blockIdx.x * EPB + 2 * w + j] = v + b2v;
        }
    }
}

extern "C" void kernel_launch(void* const* d_in, const int* in_sizes, int n_in,
                              void* d_out, int out_size) {
    const float* x        = (const float*)d_in[0];
    const float* w_nr     = (const float*)d_in[1];
    const float* b_nr     = (const float*)d_in[2];
    const float* w_r      = (const float*)d_in[3];
    const float* b_r      = (const float*)d_in[4];
    const float* w_in_nr  = (const float*)d_in[5];
    const float* b_in_nr  = (const float*)d_in[6];
    const float* w_in_r   = (const float*)d_in[7];
    const float* b_in_r   = (const float*)d_in[8];
    const float* ipw      = (const float*)d_in[9];
    const float* cw       = (const float*)d_in[10];
    const float* cb       = (const float*)d_in[11];
    const float* xpw      = (const float*)d_in[12];
    const float* dtw      = (const float*)d_in[13];
    const float* dtb      = (const float*)d_in[14];
    /* alog d_in[15] dead at L=1 (scan h0=0) */
    const float* dskip    = (const float*)d_in[16];
    const float* opw      = (const float*)d_in[17];
    const float* lng      = (const float*)d_in[18];
    const float* lnb      = (const float*)d_in[19];
    const float* hw1      = (const float*)d_in[20];
    const float* hb1      = (const float*)d_in[21];
    const float* hw2      = (const float*)d_in[22];
    const float* hb2      = (const float*)d_in[23];

    size_t smem = sizeof(Smem);
    cudaFuncSetAttribute((const void*)mamba_main,
                         cudaFuncAttributeMaxDynamicSharedMemorySize, (int)smem);

    prep_all<<<FOLD_BLKS + BLOB_BLKS, 256>>>(w_nr, b_nr, w_r, b_r, w_in_nr, w_in_r,
                                             ipw, opw, xpw, dtw, cw, cb, dtb, dskip,
                                             lng, lnb);
    mamba_main<<<NBLK, THREADS, smem>>>(x, b_in_nr, b_in_r, hw1, hb1, hw2, hb2,
                                        (float*)d_out);
}